// round 14
// baseline (speedup 1.0000x reference)
#include <cuda_runtime.h>
#include <cuda_fp16.h>
#include <math.h>

#define N_USERS 100000
#define N_ITEMS 50000
#define NNZ     1600000
#define BATCH   64
#define ORDER   8

#define NB_U ((N_USERS + 1023) / 1024)   // 98
#define NB_I ((N_ITEMS + 1023) / 1024)   // 49

#define CSR_CAP (NNZ + 4 * N_USERS)      // padded-to-4 capacity
#define CSC_CAP (NNZ + 4 * N_ITEMS)

// ---------------- device scratch (no allocation allowed) ----------------
__device__ int     cb_cnt_u[N_USERS];
__device__ int     cb_cnt_i[N_ITEMS];
__device__ int     cb_ptr_u[N_USERS + 1];
__device__ int     cb_ptr_i[N_ITEMS + 1];
__device__ int     cb_cur_u[N_USERS];
__device__ int     cb_cur_i[N_ITEMS];
__device__ __align__(16) int     cb_csr_idx[CSR_CAP];  // item idx, by user, 4-padded (pad -> N_ITEMS)
__device__ __align__(16) int     cb_csc_idx[CSC_CAP];  // user idx, by item, 4-padded (pad -> N_USERS)
__device__ __align__(128) __half2 cb_y16[(size_t)(N_USERS + 1) * 32]; // fp16 yg rows (+ zero row)
__device__ __align__(128) __half2 cb_u16[(size_t)(N_ITEMS + 1) * 32]; // fp16 u rows  (+ zero row)
__device__ __align__(16) float   cb_tA[(size_t)N_ITEMS * BATCH];     // fp32 state
__device__ __align__(16) float   cb_tB[(size_t)N_ITEMS * BATCH];
__device__ __align__(16) float   cb_acc[(size_t)N_ITEMS * BATCH];
__device__ int     cb_bsum_u[128];
__device__ int     cb_bsum_i[128];

// ---------------- fp16 pack/unpack helpers (8 values / lane) ----------------
__device__ __forceinline__ void cb_add8(float4& lo, float4& hi, uint4 v) {
    float2 f0 = __half22float2(*reinterpret_cast<const __half2*>(&v.x));
    float2 f1 = __half22float2(*reinterpret_cast<const __half2*>(&v.y));
    float2 f2 = __half22float2(*reinterpret_cast<const __half2*>(&v.z));
    float2 f3 = __half22float2(*reinterpret_cast<const __half2*>(&v.w));
    lo.x += f0.x; lo.y += f0.y; lo.z += f1.x; lo.w += f1.y;
    hi.x += f2.x; hi.y += f2.y; hi.z += f3.x; hi.w += f3.y;
}

__device__ __forceinline__ uint4 cb_pack8(float4 lo, float4 hi) {
    __half2 h0 = __float22half2_rn(make_float2(lo.x, lo.y));
    __half2 h1 = __float22half2_rn(make_float2(lo.z, lo.w));
    __half2 h2 = __float22half2_rn(make_float2(hi.x, hi.y));
    __half2 h3 = __float22half2_rn(make_float2(hi.z, hi.w));
    uint4 r;
    r.x = *reinterpret_cast<unsigned*>(&h0);
    r.y = *reinterpret_cast<unsigned*>(&h1);
    r.z = *reinterpret_cast<unsigned*>(&h2);
    r.w = *reinterpret_cast<unsigned*>(&h3);
    return r;
}

// ---------------- block-wide exclusive scan helper ----------------
__device__ __forceinline__ int cb_block_exscan(int v, int* sh) {
    int tid = threadIdx.x, lane = tid & 31, w = tid >> 5;
    int x = v;
    #pragma unroll
    for (int o = 1; o < 32; o <<= 1) {
        int t = __shfl_up_sync(0xffffffffu, x, o);
        if (lane >= o) x += t;
    }
    if (lane == 31) sh[w] = x;
    __syncthreads();
    if (w == 0) {
        int nw = blockDim.x >> 5;
        int s = (lane < nw) ? sh[lane] : 0;
        #pragma unroll
        for (int o = 1; o < 32; o <<= 1) {
            int t = __shfl_up_sync(0xffffffffu, s, o);
            if (lane >= o) s += t;
        }
        sh[lane] = s;
    }
    __syncthreads();
    int base = (w > 0) ? sh[w - 1] : 0;
    return base + x - v;   // exclusive prefix
}

// ---------------- launch 0: transpose signal + zero counts + zero dummy rows ------
__global__ void cb_transpose_in(const float* __restrict__ sig) {
    int gt  = (blockIdx.y * gridDim.x + blockIdx.x) * 1024 + threadIdx.y * 32 + threadIdx.x;
    int tot = gridDim.x * gridDim.y * 1024;
    for (int i = gt; i < N_USERS; i += tot) cb_cnt_u[i] = 0;
    for (int i = gt; i < N_ITEMS; i += tot) cb_cnt_i[i] = 0;
    if (gt < 32) {
        __half2 z = __float2half2_rn(0.0f);
        cb_u16[(size_t)N_ITEMS * 32 + gt] = z;
        cb_y16[(size_t)N_USERS * 32 + gt] = z;
    }

    __shared__ float tile[32][33];
    int item = blockIdx.x * 32 + threadIdx.x;
    int b    = blockIdx.y * 32 + threadIdx.y;
    if (item < N_ITEMS)
        tile[threadIdx.y][threadIdx.x] = sig[(size_t)b * N_ITEMS + item];
    __syncthreads();
    int itemw = blockIdx.x * 32 + threadIdx.y;
    int bw    = blockIdx.y * 32 + threadIdx.x;
    if (itemw < N_ITEMS)
        cb_tA[(size_t)itemw * BATCH + bw] = tile[threadIdx.x][threadIdx.y];
}

// ---------------- launch 1: histogram + prefill padded index arrays ----------------
__global__ void cb_hist(const int* __restrict__ row, const int* __restrict__ col) {
    int stride = gridDim.x * blockDim.x;
    int t = blockIdx.x * blockDim.x + threadIdx.x;
    for (int e = t; e < NNZ; e += stride) {
        atomicAdd(&cb_cnt_u[row[e]], 1);
        atomicAdd(&cb_cnt_i[col[e]], 1);
    }
    for (int i = t; i < CSR_CAP; i += stride) cb_csr_idx[i] = N_ITEMS;  // -> zero row
    for (int i = t; i < CSC_CAP; i += stride) cb_csc_idx[i] = N_USERS;  // -> zero row
}

// ---------------- launch 2: per-block sums of PADDED counts ----------------
__global__ void cb_blocksum() {
    __shared__ int sh[32];
    bool isU = blockIdx.x < NB_U;
    int  b   = isU ? blockIdx.x : blockIdx.x - NB_U;
    const int* cnt = isU ? cb_cnt_u : cb_cnt_i;
    int  n   = isU ? N_USERS : N_ITEMS;
    int  i   = b * 1024 + threadIdx.x;
    int  v   = (i < n) ? ((cnt[i] + 3) & ~3) : 0;
    #pragma unroll
    for (int o = 16; o; o >>= 1) v += __shfl_down_sync(0xffffffffu, v, o);
    if ((threadIdx.x & 31) == 0) sh[threadIdx.x >> 5] = v;
    __syncthreads();
    if (threadIdx.x < 32) {
        int s = (threadIdx.x < (blockDim.x >> 5)) ? sh[threadIdx.x] : 0;
        #pragma unroll
        for (int o = 16; o; o >>= 1) s += __shfl_down_sync(0xffffffffu, s, o);
        if (threadIdx.x == 0) (isU ? cb_bsum_u : cb_bsum_i)[b] = s;
    }
}

// ---------------- launch 3: scan the block sums (single block) ----------------
__global__ void cb_scan_bsums() {
    __shared__ int sh[32];
    int t = threadIdx.x;
    int v = (t < NB_U) ? cb_bsum_u[t] : 0;
    int ex = cb_block_exscan(v, sh);
    if (t < NB_U) cb_bsum_u[t] = ex;
    __syncthreads();
    int v2 = (t < NB_I) ? cb_bsum_i[t] : 0;
    int ex2 = cb_block_exscan(v2, sh);
    if (t < NB_I) cb_bsum_i[t] = ex2;
}

// ---------------- launch 4: final scan of PADDED counts -> ptr, cur ----------------
__global__ void cb_scan_final() {
    __shared__ int sh[32];
    bool isU = blockIdx.x < NB_U;
    int  b   = isU ? blockIdx.x : blockIdx.x - NB_U;
    const int* cnt   = isU ? cb_cnt_u  : cb_cnt_i;
    const int* bscan = isU ? cb_bsum_u : cb_bsum_i;
    int*       ptr   = isU ? cb_ptr_u  : cb_ptr_i;
    int*       cur   = isU ? cb_cur_u  : cb_cur_i;
    int  n   = isU ? N_USERS : N_ITEMS;
    int  i   = b * 1024 + threadIdx.x;
    int  v   = (i < n) ? ((cnt[i] + 3) & ~3) : 0;
    int  ex  = cb_block_exscan(v, sh);
    if (i < n) {
        int p = bscan[b] + ex;
        ptr[i] = p;
        cur[i] = p;
        if (i == n - 1) ptr[n] = p + v;
    }
}

// ---------------- launch 5: scatter edges + u0 = di^-1/2 * s (fp32 + fp16 mirror) ----
__global__ void cb_scatter(const int* __restrict__ row, const int* __restrict__ col) {
    int stride = gridDim.x * blockDim.x;
    int t = blockIdx.x * blockDim.x + threadIdx.x;
    for (int e = t; e < NNZ; e += stride) {
        int r = row[e], c = col[e];
        cb_csr_idx[atomicAdd(&cb_cur_u[r], 1)] = c;
        cb_csc_idx[atomicAdd(&cb_cur_i[c], 1)] = r;
    }
    float2* tA2 = (float2*)cb_tA;
    for (int i = t; i < N_ITEMS * 32; i += stride) {
        int item = i >> 5;
        int cnt  = cb_cnt_i[item];
        float s  = (cnt > 0) ? rsqrtf((float)cnt) : 0.0f;
        float2 v = tA2[i];
        v.x *= s; v.y *= s;
        tA2[i] = v;
        cb_u16[i] = __float22half2_rn(v);
    }
}

// ---------------- SpMM user side: quarter-warp per row (8 lanes x uint4 = 128 B) ----
// Four independent row chains per warp; 1 wavefront/edge; no cross-lane reduction.
__global__ __launch_bounds__(256) void cb_spmmA() {
    int gw  = (blockIdx.x * blockDim.x + threadIdx.x) >> 3;  // user row per quarter-warp
    int sub = threadIdx.x & 7;                               // owns batch cols 8*sub..8*sub+7
    if (gw >= N_USERS) return;
    int e = cb_ptr_u[gw], end = cb_ptr_u[gw + 1];
    if (e == end) return;
    const int4* ip = (const int4*)(cb_csr_idx + e);
    const uint4* src = (const uint4*)cb_u16;   // row stride = 8 uint4 (128 B)
    int nq = (end - e) >> 2;
    float4 a0l = {0,0,0,0}, a0h = {0,0,0,0};
    float4 a1l = {0,0,0,0}, a1h = {0,0,0,0};
    float4 a2l = {0,0,0,0}, a2h = {0,0,0,0};
    float4 a3l = {0,0,0,0}, a3h = {0,0,0,0};
    for (int q = 0; q < nq; q++) {
        int4 c = __ldg(ip + q);
        uint4 v0 = __ldg(src + (size_t)c.x * 8 + sub);
        uint4 v1 = __ldg(src + (size_t)c.y * 8 + sub);
        uint4 v2 = __ldg(src + (size_t)c.z * 8 + sub);
        uint4 v3 = __ldg(src + (size_t)c.w * 8 + sub);
        cb_add8(a0l, a0h, v0);
        cb_add8(a1l, a1h, v1);
        cb_add8(a2l, a2h, v2);
        cb_add8(a3l, a3h, v3);
    }
    float inv = 1.0f / (float)cb_cnt_u[gw];
    float4 rl, rh;
    rl.x = ((a0l.x + a1l.x) + (a2l.x + a3l.x)) * inv;
    rl.y = ((a0l.y + a1l.y) + (a2l.y + a3l.y)) * inv;
    rl.z = ((a0l.z + a1l.z) + (a2l.z + a3l.z)) * inv;
    rl.w = ((a0l.w + a1l.w) + (a2l.w + a3l.w)) * inv;
    rh.x = ((a0h.x + a1h.x) + (a2h.x + a3h.x)) * inv;
    rh.y = ((a0h.y + a1h.y) + (a2h.y + a3h.y)) * inv;
    rh.z = ((a0h.z + a1h.z) + (a2h.z + a3h.z)) * inv;
    rh.w = ((a0h.w + a1h.w) + (a2h.w + a3h.w)) * inv;
    ((uint4*)cb_y16)[(size_t)gw * 8 + sub] = cb_pack8(rl, rh);
}

// gather z_raw[item] = sum_e y16[row_e]   (fp32 accumulate, quarter-warp per item)
__device__ __forceinline__ void cb_gather_z(int e, int end, int sub,
                                            float4& zl, float4& zh) {
    const int4* ip = (const int4*)(cb_csc_idx + e);
    const uint4* src = (const uint4*)cb_y16;
    int nq = (end - e) >> 2;
    float4 a0l = {0,0,0,0}, a0h = {0,0,0,0};
    float4 a1l = {0,0,0,0}, a1h = {0,0,0,0};
    float4 a2l = {0,0,0,0}, a2h = {0,0,0,0};
    float4 a3l = {0,0,0,0}, a3h = {0,0,0,0};
    for (int q = 0; q < nq; q++) {
        int4 c = __ldg(ip + q);
        uint4 v0 = __ldg(src + (size_t)c.x * 8 + sub);
        uint4 v1 = __ldg(src + (size_t)c.y * 8 + sub);
        uint4 v2 = __ldg(src + (size_t)c.z * 8 + sub);
        uint4 v3 = __ldg(src + (size_t)c.w * 8 + sub);
        cb_add8(a0l, a0h, v0);
        cb_add8(a1l, a1h, v1);
        cb_add8(a2l, a2h, v2);
        cb_add8(a3l, a3h, v3);
    }
    zl.x = (a0l.x + a1l.x) + (a2l.x + a3l.x);
    zl.y = (a0l.y + a1l.y) + (a2l.y + a3l.y);
    zl.z = (a0l.z + a1l.z) + (a2l.z + a3l.z);
    zl.w = (a0l.w + a1l.w) + (a2l.w + a3l.w);
    zh.x = (a0h.x + a1h.x) + (a2h.x + a3h.x);
    zh.y = (a0h.y + a1h.y) + (a2h.y + a3h.y);
    zh.z = (a0h.z + a1h.z) + (a2h.z + a3h.z);
    zh.w = (a0h.w + a1h.w) + (a2h.w + a3h.w);
}

// First step: u1 = u0 - 2*z/deg ; acc = c0*u0 + c1*u1 ; u16 = fp16(u1)
__global__ __launch_bounds__(256) void cb_spmmAT_first(const float* __restrict__ u0,
                                                       float* __restrict__ u1,
                                                       float c0, float c1) {
    int item = (blockIdx.x * blockDim.x + threadIdx.x) >> 3;
    int sub  = threadIdx.x & 7;
    if (item >= N_ITEMS) return;
    int e = cb_ptr_i[item], end = cb_ptr_i[item + 1];
    float4 zl = {0,0,0,0}, zh = {0,0,0,0};
    if (e < end) cb_gather_z(e, end, sub, zl, zh);
    int n = cb_cnt_i[item];
    float sc2 = (n > 0) ? 2.0f / (float)n : 0.0f;
    size_t i = (size_t)item * 16 + sub * 2;   // float4 index (16 per row)
    float4 sL = ((const float4*)u0)[i];
    float4 sH = ((const float4*)u0)[i + 1];
    float4 tL, tH;
    tL.x = fmaf(-sc2, zl.x, sL.x); tL.y = fmaf(-sc2, zl.y, sL.y);
    tL.z = fmaf(-sc2, zl.z, sL.z); tL.w = fmaf(-sc2, zl.w, sL.w);
    tH.x = fmaf(-sc2, zh.x, sH.x); tH.y = fmaf(-sc2, zh.y, sH.y);
    tH.z = fmaf(-sc2, zh.z, sH.z); tH.w = fmaf(-sc2, zh.w, sH.w);
    ((float4*)u1)[i]     = tL;
    ((float4*)u1)[i + 1] = tH;
    ((uint4*)cb_u16)[(size_t)item * 8 + sub] = cb_pack8(tL, tH);
    float4 aL, aH;
    aL.x = c0 * sL.x + c1 * tL.x; aL.y = c0 * sL.y + c1 * tL.y;
    aL.z = c0 * sL.z + c1 * tL.z; aL.w = c0 * sL.w + c1 * tL.w;
    aH.x = c0 * sH.x + c1 * tH.x; aH.y = c0 * sH.y + c1 * tH.y;
    aH.z = c0 * sH.z + c1 * tH.z; aH.w = c0 * sH.w + c1 * tH.w;
    ((float4*)cb_acc)[i]     = aL;
    ((float4*)cb_acc)[i + 1] = aH;
}

// Step k: u2 = 2*u1 - 4*z/deg - u0 ; acc += ck*u2 ; u2 overwrites u0 ; u16 = fp16(u2)
__global__ __launch_bounds__(256) void cb_spmmAT_step(const float* __restrict__ ucur,
                                                      float* __restrict__ uprev,
                                                      float ck) {
    int item = (blockIdx.x * blockDim.x + threadIdx.x) >> 3;
    int sub  = threadIdx.x & 7;
    if (item >= N_ITEMS) return;
    int e = cb_ptr_i[item], end = cb_ptr_i[item + 1];
    float4 zl = {0,0,0,0}, zh = {0,0,0,0};
    if (e < end) cb_gather_z(e, end, sub, zl, zh);
    int n = cb_cnt_i[item];
    float sc4 = (n > 0) ? 4.0f / (float)n : 0.0f;
    size_t i = (size_t)item * 16 + sub * 2;
    float4 c1L = ((const float4*)ucur)[i];
    float4 c1H = ((const float4*)ucur)[i + 1];
    float4 p0L = ((const float4*)uprev)[i];
    float4 p0H = ((const float4*)uprev)[i + 1];
    float4 t2L, t2H;
    t2L.x = 2.f * c1L.x - sc4 * zl.x - p0L.x;
    t2L.y = 2.f * c1L.y - sc4 * zl.y - p0L.y;
    t2L.z = 2.f * c1L.z - sc4 * zl.z - p0L.z;
    t2L.w = 2.f * c1L.w - sc4 * zl.w - p0L.w;
    t2H.x = 2.f * c1H.x - sc4 * zh.x - p0H.x;
    t2H.y = 2.f * c1H.y - sc4 * zh.y - p0H.y;
    t2H.z = 2.f * c1H.z - sc4 * zh.z - p0H.z;
    t2H.w = 2.f * c1H.w - sc4 * zh.w - p0H.w;
    ((float4*)uprev)[i]     = t2L;
    ((float4*)uprev)[i + 1] = t2H;
    ((uint4*)cb_u16)[(size_t)item * 8 + sub] = cb_pack8(t2L, t2H);
    float4 aL = ((float4*)cb_acc)[i];
    float4 aH = ((float4*)cb_acc)[i + 1];
    aL.x += ck * t2L.x; aL.y += ck * t2L.y; aL.z += ck * t2L.z; aL.w += ck * t2L.w;
    aH.x += ck * t2H.x; aH.y += ck * t2H.y; aH.z += ck * t2H.z; aH.w += ck * t2H.w;
    ((float4*)cb_acc)[i]     = aL;
    ((float4*)cb_acc)[i + 1] = aH;
}

// ---------------- final: out[b][item] = acc*sqrt(deg)  (deg0: sumc * s) ----------------
__global__ void cb_transpose_out(float* __restrict__ dst, const float* __restrict__ sig,
                                 float sumc) {
    __shared__ float tile[32][33];
    int b    = blockIdx.y * 32 + threadIdx.x;
    int item = blockIdx.x * 32 + threadIdx.y;
    if (item < N_ITEMS) {
        int cnt = cb_cnt_i[item];
        float s = (cnt > 0) ? sqrtf((float)cnt) : 0.0f;
        tile[threadIdx.y][threadIdx.x] = cb_acc[(size_t)item * BATCH + b] * s;
    }
    __syncthreads();
    int itemw = blockIdx.x * 32 + threadIdx.x;
    int bw    = blockIdx.y * 32 + threadIdx.y;
    if (itemw < N_ITEMS) {
        float v;
        if (cb_cnt_i[itemw] > 0) v = tile[threadIdx.x][threadIdx.y];
        else                     v = sumc * sig[(size_t)bw * N_ITEMS + itemw];
        dst[(size_t)bw * N_ITEMS + itemw] = v;
    }
}

// ---------------- host side ----------------
static inline double cb_rnd3(double v) { return rint(v * 1000.0) / 1000.0; }

static void cb_coeffs(float* cf) {
    const int order = 8, flat = 2;
    double xv[9], tgt[9], nodes[9];
    for (int x = 0; x <= order; x++)
        xv[x] = cb_rnd3(cos((double)(order - x) / order * M_PI));
    for (int i = 0; i <= order; i++) {
        double t = (xv[i] < 0.0) ? pow(-xv[i], (double)flat) * 0.5 + 0.5
                                 : pow(xv[i], (double)flat) * (-0.5) + 0.5;
        tgt[i] = cb_rnd3(t);
    }
    for (int k = 1; k <= order + 1; k++)
        nodes[k - 1] = cos((order + 1 + 0.5 - k) / (double)(order + 1) * M_PI);
    double prev[9], cur[9], nxt[9];
    double c[9];
    double s0 = 0.0, s1 = 0.0;
    for (int i = 0; i <= order; i++) {
        prev[i] = tgt[i];
        cur[i]  = nodes[i] * tgt[i];
        s0 += prev[i];
        s1 += cur[i];
    }
    c[0] = s0 * (2.0 / (order + 1)) / 2.0;
    c[1] = s1 * (2.0 / (order + 1));
    for (int m = 2; m <= order; m++) {
        double sm = 0.0;
        for (int i = 0; i <= order; i++) {
            nxt[i] = nodes[i] * cur[i] * 2.0 - prev[i];
            sm += nxt[i];
        }
        c[m] = sm * (2.0 / (order + 1));
        for (int i = 0; i <= order; i++) { prev[i] = cur[i]; cur[i] = nxt[i]; }
    }
    for (int m = 0; m <= order; m++) cf[m] = (float)c[m];
}

extern "C" void kernel_launch(void* const* d_in, const int* in_sizes, int n_in,
                              void* d_out, int out_size) {
    const float* signal = (const float*)d_in[0];
    const int*   row    = (const int*)d_in[2];
    const int*   col    = (const int*)d_in[3];
    float*       out    = (float*)d_out;

    float cf[ORDER + 1];
    cb_coeffs(cf);
    float sumc = 0.f;
    for (int k = 0; k <= ORDER; k++) sumc += cf[k];

    float *tA, *tB;
    cudaGetSymbolAddress((void**)&tA, cb_tA);
    cudaGetSymbolAddress((void**)&tB, cb_tB);

    dim3 tb(32, 32);
    dim3 tg((N_ITEMS + 31) / 32, (BATCH + 31) / 32);

    // ---- build + prep ----
    cb_transpose_in<<<tg, tb>>>(signal);             // transpose + zero counts + zero rows
    cb_hist<<<2048, 256>>>(row, col);                // histogram + prefill pad indices
    cb_blocksum<<<NB_U + NB_I, 1024>>>();
    cb_scan_bsums<<<1, 128>>>();
    cb_scan_final<<<NB_U + NB_I, 1024>>>();
    cb_scatter<<<2048, 256>>>(row, col);             // scatter + scale u0 + u16 mirror

    const int GA = (N_USERS * 8 + 255) / 256;  // quarter-warp per user row
    const int GI = (N_ITEMS * 8 + 255) / 256;  // quarter-warp per item row

    // ---- Chebyshev recurrence (scaled domain; fp16 gather, quarter-warp rows) ----
    cb_spmmA<<<GA, 256>>>();
    cb_spmmAT_first<<<GI, 256>>>(tA, tB, cf[0], cf[1]);
    float* t0p = tA;
    float* t1p = tB;
    for (int k = 2; k <= ORDER; k++) {
        cb_spmmA<<<GA, 256>>>();
        cb_spmmAT_step<<<GI, 256>>>(t1p, t0p, cf[k]);
        float* tmp = t0p; t0p = t1p; t1p = tmp;   // (t0,t1) <- (t1,t2)
    }

    // ---- final transpose to [BATCH, N_ITEMS] ----
    cb_transpose_out<<<tg, tb>>>(out, signal, sumc);
}

// round 15
// speedup vs baseline: 1.0759x; 1.0759x over previous
#include <cuda_runtime.h>
#include <cuda_fp16.h>
#include <math.h>

#define N_USERS 100000
#define N_ITEMS 50000
#define NNZ     1600000
#define BATCH   64
#define ORDER   8

#define NB_U ((N_USERS + 1023) / 1024)   // 98
#define NB_I ((N_ITEMS + 1023) / 1024)   // 49

#define CSR_CAP (NNZ + 4 * N_USERS)      // padded-to-4 capacity
#define CSC_CAP (NNZ + 4 * N_ITEMS)

// ---------------- device scratch (no allocation allowed) ----------------
__device__ int     cb_cnt_u[N_USERS];
__device__ int     cb_cnt_i[N_ITEMS];
__device__ int     cb_ptr_u[N_USERS + 1];
__device__ int     cb_ptr_i[N_ITEMS + 1];
__device__ int     cb_cur_u[N_USERS];
__device__ int     cb_cur_i[N_ITEMS];
__device__ __align__(16) int     cb_csr_idx[CSR_CAP];  // item idx, by user, 4-padded (pad -> N_ITEMS)
__device__ __align__(16) int     cb_csc_idx[CSC_CAP];  // user idx, by item, 4-padded (pad -> N_USERS)
__device__ __align__(128) __half2 cb_y16[(size_t)(N_USERS + 1) * 32]; // fp16 yg rows (+ zero row)
__device__ __align__(128) __half2 cb_u16[(size_t)(N_ITEMS + 1) * 32]; // fp16 u rows  (+ zero row)
__device__ __align__(16) float   cb_tA[(size_t)N_ITEMS * BATCH];     // fp32 state
__device__ __align__(16) float   cb_tB[(size_t)N_ITEMS * BATCH];
__device__ __align__(16) float   cb_acc[(size_t)N_ITEMS * BATCH];
__device__ int     cb_bsum_u[128];
__device__ int     cb_bsum_i[128];

// ---------------- fp16 pack/unpack helpers (4 values / lane) ----------------
__device__ __forceinline__ void cb_add4(float4& a, uint2 v) {
    float2 f0 = __half22float2(*reinterpret_cast<const __half2*>(&v.x));
    float2 f1 = __half22float2(*reinterpret_cast<const __half2*>(&v.y));
    a.x += f0.x; a.y += f0.y; a.z += f1.x; a.w += f1.y;
}

__device__ __forceinline__ uint2 cb_pack4(float4 v) {
    __half2 h0 = __float22half2_rn(make_float2(v.x, v.y));
    __half2 h1 = __float22half2_rn(make_float2(v.z, v.w));
    uint2 r;
    r.x = *reinterpret_cast<unsigned*>(&h0);
    r.y = *reinterpret_cast<unsigned*>(&h1);
    return r;
}

// ---------------- block-wide exclusive scan helper ----------------
__device__ __forceinline__ int cb_block_exscan(int v, int* sh) {
    int tid = threadIdx.x, lane = tid & 31, w = tid >> 5;
    int x = v;
    #pragma unroll
    for (int o = 1; o < 32; o <<= 1) {
        int t = __shfl_up_sync(0xffffffffu, x, o);
        if (lane >= o) x += t;
    }
    if (lane == 31) sh[w] = x;
    __syncthreads();
    if (w == 0) {
        int nw = blockDim.x >> 5;
        int s = (lane < nw) ? sh[lane] : 0;
        #pragma unroll
        for (int o = 1; o < 32; o <<= 1) {
            int t = __shfl_up_sync(0xffffffffu, s, o);
            if (lane >= o) s += t;
        }
        sh[lane] = s;
    }
    __syncthreads();
    int base = (w > 0) ? sh[w - 1] : 0;
    return base + x - v;   // exclusive prefix
}

// ---------------- launch 0: transpose signal + zero counts + zero dummy rows ------
__global__ void cb_transpose_in(const float* __restrict__ sig) {
    int gt  = (blockIdx.y * gridDim.x + blockIdx.x) * 1024 + threadIdx.y * 32 + threadIdx.x;
    int tot = gridDim.x * gridDim.y * 1024;
    for (int i = gt; i < N_USERS; i += tot) cb_cnt_u[i] = 0;
    for (int i = gt; i < N_ITEMS; i += tot) cb_cnt_i[i] = 0;
    if (gt < 32) {
        __half2 z = __float2half2_rn(0.0f);
        cb_u16[(size_t)N_ITEMS * 32 + gt] = z;
        cb_y16[(size_t)N_USERS * 32 + gt] = z;
    }

    __shared__ float tile[32][33];
    int item = blockIdx.x * 32 + threadIdx.x;
    int b    = blockIdx.y * 32 + threadIdx.y;
    if (item < N_ITEMS)
        tile[threadIdx.y][threadIdx.x] = sig[(size_t)b * N_ITEMS + item];
    __syncthreads();
    int itemw = blockIdx.x * 32 + threadIdx.y;
    int bw    = blockIdx.y * 32 + threadIdx.x;
    if (itemw < N_ITEMS)
        cb_tA[(size_t)itemw * BATCH + bw] = tile[threadIdx.x][threadIdx.y];
}

// ---------------- launch 1: histogram ----------------
__global__ void cb_hist(const int* __restrict__ row, const int* __restrict__ col) {
    int stride = gridDim.x * blockDim.x;
    int t = blockIdx.x * blockDim.x + threadIdx.x;
    for (int e = t; e < NNZ; e += stride) {
        atomicAdd(&cb_cnt_u[row[e]], 1);
        atomicAdd(&cb_cnt_i[col[e]], 1);
    }
}

// ---------------- launch 2: per-block sums of PADDED counts ----------------
__global__ void cb_blocksum() {
    __shared__ int sh[32];
    bool isU = blockIdx.x < NB_U;
    int  b   = isU ? blockIdx.x : blockIdx.x - NB_U;
    const int* cnt = isU ? cb_cnt_u : cb_cnt_i;
    int  n   = isU ? N_USERS : N_ITEMS;
    int  i   = b * 1024 + threadIdx.x;
    int  v   = (i < n) ? ((cnt[i] + 3) & ~3) : 0;
    #pragma unroll
    for (int o = 16; o; o >>= 1) v += __shfl_down_sync(0xffffffffu, v, o);
    if ((threadIdx.x & 31) == 0) sh[threadIdx.x >> 5] = v;
    __syncthreads();
    if (threadIdx.x < 32) {
        int s = (threadIdx.x < (blockDim.x >> 5)) ? sh[threadIdx.x] : 0;
        #pragma unroll
        for (int o = 16; o; o >>= 1) s += __shfl_down_sync(0xffffffffu, s, o);
        if (threadIdx.x == 0) (isU ? cb_bsum_u : cb_bsum_i)[b] = s;
    }
}

// ---------------- launch 3: scan the block sums (single block) ----------------
__global__ void cb_scan_bsums() {
    __shared__ int sh[32];
    int t = threadIdx.x;
    int v = (t < NB_U) ? cb_bsum_u[t] : 0;
    int ex = cb_block_exscan(v, sh);
    if (t < NB_U) cb_bsum_u[t] = ex;
    __syncthreads();
    int v2 = (t < NB_I) ? cb_bsum_i[t] : 0;
    int ex2 = cb_block_exscan(v2, sh);
    if (t < NB_I) cb_bsum_i[t] = ex2;
}

// ---------------- launch 4: final scan -> ptr, cur + write pad slots ----------------
__global__ void cb_scan_final() {
    __shared__ int sh[32];
    bool isU = blockIdx.x < NB_U;
    int  b   = isU ? blockIdx.x : blockIdx.x - NB_U;
    const int* cnt   = isU ? cb_cnt_u  : cb_cnt_i;
    const int* bscan = isU ? cb_bsum_u : cb_bsum_i;
    int*       ptr   = isU ? cb_ptr_u  : cb_ptr_i;
    int*       cur   = isU ? cb_cur_u  : cb_cur_i;
    int*       idx   = isU ? cb_csr_idx : cb_csc_idx;
    int        dummy = isU ? N_ITEMS   : N_USERS;
    int  n   = isU ? N_USERS : N_ITEMS;
    int  i   = b * 1024 + threadIdx.x;
    int  c   = (i < n) ? cnt[i] : 0;
    int  v   = (c + 3) & ~3;
    int  ex  = cb_block_exscan(v, sh);
    if (i < n) {
        int p = bscan[b] + ex;
        ptr[i] = p;
        cur[i] = p;
        // fill pad slots [p + c, p + v) with dummy index (-> zero row)
        for (int j = p + c; j < p + v; j++) idx[j] = dummy;
        if (i == n - 1) ptr[n] = p + v;
    }
}

// ---------------- launch 5: scatter edges + u0 = di^-1/2 * s (fp32 + fp16 mirror) ----
__global__ void cb_scatter(const int* __restrict__ row, const int* __restrict__ col) {
    int stride = gridDim.x * blockDim.x;
    int t = blockIdx.x * blockDim.x + threadIdx.x;
    for (int e = t; e < NNZ; e += stride) {
        int r = row[e], c = col[e];
        cb_csr_idx[atomicAdd(&cb_cur_u[r], 1)] = c;
        cb_csc_idx[atomicAdd(&cb_cur_i[c], 1)] = r;
    }
    float2* tA2 = (float2*)cb_tA;
    for (int i = t; i < N_ITEMS * 32; i += stride) {
        int item = i >> 5;
        int cnt  = cb_cnt_i[item];
        float s  = (cnt > 0) ? rsqrtf((float)cnt) : 0.0f;
        float2 v = tA2[i];
        v.x *= s; v.y *= s;
        tA2[i] = v;
        cb_u16[i] = __float22half2_rn(v);
    }
}

// ---------------- SpMM user side: half-warp per row (16 lanes x uint2 = 128 B) ------
// Two independent row chains per warp -> 2x row-level MLP, same wavefronts.
__global__ __launch_bounds__(256) void cb_spmmA() {
    int gw  = (blockIdx.x * blockDim.x + threadIdx.x) >> 4;  // user row per half-warp
    int sub = threadIdx.x & 15;                              // owns batch cols 4*sub..4*sub+3
    if (gw >= N_USERS) return;
    int e = cb_ptr_u[gw], end = cb_ptr_u[gw + 1];
    if (e == end) return;
    const int4* ip = (const int4*)(cb_csr_idx + e);
    const uint2* src = (const uint2*)cb_u16;   // row stride = 16 uint2 (128 B)
    int nq = (end - e) >> 2;
    float4 a0 = {0,0,0,0}, a1 = {0,0,0,0}, a2 = {0,0,0,0}, a3 = {0,0,0,0};
    for (int q = 0; q < nq; q++) {
        int4 c = __ldg(ip + q);
        uint2 v0 = __ldg(src + (size_t)c.x * 16 + sub);
        uint2 v1 = __ldg(src + (size_t)c.y * 16 + sub);
        uint2 v2 = __ldg(src + (size_t)c.z * 16 + sub);
        uint2 v3 = __ldg(src + (size_t)c.w * 16 + sub);
        cb_add4(a0, v0);
        cb_add4(a1, v1);
        cb_add4(a2, v2);
        cb_add4(a3, v3);
    }
    float inv = 1.0f / (float)cb_cnt_u[gw];
    float4 r;
    r.x = ((a0.x + a1.x) + (a2.x + a3.x)) * inv;
    r.y = ((a0.y + a1.y) + (a2.y + a3.y)) * inv;
    r.z = ((a0.z + a1.z) + (a2.z + a3.z)) * inv;
    r.w = ((a0.w + a1.w) + (a2.w + a3.w)) * inv;
    ((uint2*)cb_y16)[(size_t)gw * 16 + sub] = cb_pack4(r);
}

// gather z_raw[item] = sum_e y16[row_e]   (fp32 accumulate, half-warp per item)
__device__ __forceinline__ float4 cb_gather_z(int e, int end, int sub) {
    const int4* ip = (const int4*)(cb_csc_idx + e);
    const uint2* src = (const uint2*)cb_y16;
    int nq = (end - e) >> 2;
    float4 a0 = {0,0,0,0}, a1 = {0,0,0,0}, a2 = {0,0,0,0}, a3 = {0,0,0,0};
    for (int q = 0; q < nq; q++) {
        int4 c = __ldg(ip + q);
        uint2 v0 = __ldg(src + (size_t)c.x * 16 + sub);
        uint2 v1 = __ldg(src + (size_t)c.y * 16 + sub);
        uint2 v2 = __ldg(src + (size_t)c.z * 16 + sub);
        uint2 v3 = __ldg(src + (size_t)c.w * 16 + sub);
        cb_add4(a0, v0);
        cb_add4(a1, v1);
        cb_add4(a2, v2);
        cb_add4(a3, v3);
    }
    float4 z;
    z.x = (a0.x + a1.x) + (a2.x + a3.x);
    z.y = (a0.y + a1.y) + (a2.y + a3.y);
    z.z = (a0.z + a1.z) + (a2.z + a3.z);
    z.w = (a0.w + a1.w) + (a2.w + a3.w);
    return z;
}

// First step: u1 = u0 - 2*z/deg ; acc = c0*u0 + c1*u1 ; u16 = fp16(u1)
__global__ __launch_bounds__(256) void cb_spmmAT_first(const float* __restrict__ u0,
                                                       float* __restrict__ u1,
                                                       float c0, float c1) {
    int item = (blockIdx.x * blockDim.x + threadIdx.x) >> 4;
    int sub  = threadIdx.x & 15;
    if (item >= N_ITEMS) return;
    int e = cb_ptr_i[item], end = cb_ptr_i[item + 1];
    float4 z = {0.f, 0.f, 0.f, 0.f};
    if (e < end) z = cb_gather_z(e, end, sub);
    int n = cb_cnt_i[item];
    float sc2 = (n > 0) ? 2.0f / (float)n : 0.0f;
    size_t i = (size_t)item * 16 + sub;   // float4 index (16 per row)
    float4 s = ((const float4*)u0)[i];
    float4 t1;
    t1.x = fmaf(-sc2, z.x, s.x);
    t1.y = fmaf(-sc2, z.y, s.y);
    t1.z = fmaf(-sc2, z.z, s.z);
    t1.w = fmaf(-sc2, z.w, s.w);
    ((float4*)u1)[i] = t1;
    ((uint2*)cb_u16)[i] = cb_pack4(t1);
    float4 ac;
    ac.x = c0 * s.x + c1 * t1.x;
    ac.y = c0 * s.y + c1 * t1.y;
    ac.z = c0 * s.z + c1 * t1.z;
    ac.w = c0 * s.w + c1 * t1.w;
    ((float4*)cb_acc)[i] = ac;
}

// Step k: u2 = 2*u1 - 4*z/deg - u0 ; acc += ck*u2 ; u2 overwrites u0 ; u16 = fp16(u2)
__global__ __launch_bounds__(256) void cb_spmmAT_step(const float* __restrict__ ucur,
                                                      float* __restrict__ uprev,
                                                      float ck) {
    int item = (blockIdx.x * blockDim.x + threadIdx.x) >> 4;
    int sub  = threadIdx.x & 15;
    if (item >= N_ITEMS) return;
    int e = cb_ptr_i[item], end = cb_ptr_i[item + 1];
    float4 z = {0.f, 0.f, 0.f, 0.f};
    if (e < end) z = cb_gather_z(e, end, sub);
    int n = cb_cnt_i[item];
    float sc4 = (n > 0) ? 4.0f / (float)n : 0.0f;
    size_t i = (size_t)item * 16 + sub;
    float4 t1v = ((const float4*)ucur)[i];
    float4 t0v = ((const float4*)uprev)[i];
    float4 t2;
    t2.x = 2.f * t1v.x - sc4 * z.x - t0v.x;
    t2.y = 2.f * t1v.y - sc4 * z.y - t0v.y;
    t2.z = 2.f * t1v.z - sc4 * z.z - t0v.z;
    t2.w = 2.f * t1v.w - sc4 * z.w - t0v.w;
    ((float4*)uprev)[i] = t2;
    ((uint2*)cb_u16)[i] = cb_pack4(t2);
    float4 ac = ((float4*)cb_acc)[i];
    ac.x += ck * t2.x;
    ac.y += ck * t2.y;
    ac.z += ck * t2.z;
    ac.w += ck * t2.w;
    ((float4*)cb_acc)[i] = ac;
}

// ---------------- final: out[b][item] = acc*sqrt(deg)  (deg0: sumc * s) ----------------
__global__ void cb_transpose_out(float* __restrict__ dst, const float* __restrict__ sig,
                                 float sumc) {
    __shared__ float tile[32][33];
    int b    = blockIdx.y * 32 + threadIdx.x;
    int item = blockIdx.x * 32 + threadIdx.y;
    if (item < N_ITEMS) {
        int cnt = cb_cnt_i[item];
        float s = (cnt > 0) ? sqrtf((float)cnt) : 0.0f;
        tile[threadIdx.y][threadIdx.x] = cb_acc[(size_t)item * BATCH + b] * s;
    }
    __syncthreads();
    int itemw = blockIdx.x * 32 + threadIdx.x;
    int bw    = blockIdx.y * 32 + threadIdx.y;
    if (itemw < N_ITEMS) {
        float v;
        if (cb_cnt_i[itemw] > 0) v = tile[threadIdx.x][threadIdx.y];
        else                     v = sumc * sig[(size_t)bw * N_ITEMS + itemw];
        dst[(size_t)bw * N_ITEMS + itemw] = v;
    }
}

// ---------------- host side ----------------
static inline double cb_rnd3(double v) { return rint(v * 1000.0) / 1000.0; }

static void cb_coeffs(float* cf) {
    const int order = 8, flat = 2;
    double xv[9], tgt[9], nodes[9];
    for (int x = 0; x <= order; x++)
        xv[x] = cb_rnd3(cos((double)(order - x) / order * M_PI));
    for (int i = 0; i <= order; i++) {
        double t = (xv[i] < 0.0) ? pow(-xv[i], (double)flat) * 0.5 + 0.5
                                 : pow(xv[i], (double)flat) * (-0.5) + 0.5;
        tgt[i] = cb_rnd3(t);
    }
    for (int k = 1; k <= order + 1; k++)
        nodes[k - 1] = cos((order + 1 + 0.5 - k) / (double)(order + 1) * M_PI);
    double prev[9], cur[9], nxt[9];
    double c[9];
    double s0 = 0.0, s1 = 0.0;
    for (int i = 0; i <= order; i++) {
        prev[i] = tgt[i];
        cur[i]  = nodes[i] * tgt[i];
        s0 += prev[i];
        s1 += cur[i];
    }
    c[0] = s0 * (2.0 / (order + 1)) / 2.0;
    c[1] = s1 * (2.0 / (order + 1));
    for (int m = 2; m <= order; m++) {
        double sm = 0.0;
        for (int i = 0; i <= order; i++) {
            nxt[i] = nodes[i] * cur[i] * 2.0 - prev[i];
            sm += nxt[i];
        }
        c[m] = sm * (2.0 / (order + 1));
        for (int i = 0; i <= order; i++) { prev[i] = cur[i]; cur[i] = nxt[i]; }
    }
    for (int m = 0; m <= order; m++) cf[m] = (float)c[m];
}

extern "C" void kernel_launch(void* const* d_in, const int* in_sizes, int n_in,
                              void* d_out, int out_size) {
    const float* signal = (const float*)d_in[0];
    const int*   row    = (const int*)d_in[2];
    const int*   col    = (const int*)d_in[3];
    float*       out    = (float*)d_out;

    float cf[ORDER + 1];
    cb_coeffs(cf);
    float sumc = 0.f;
    for (int k = 0; k <= ORDER; k++) sumc += cf[k];

    float *tA, *tB;
    cudaGetSymbolAddress((void**)&tA, cb_tA);
    cudaGetSymbolAddress((void**)&tB, cb_tB);

    dim3 tb(32, 32);
    dim3 tg((N_ITEMS + 31) / 32, (BATCH + 31) / 32);

    // ---- build + prep ----
    cb_transpose_in<<<tg, tb>>>(signal);             // transpose + zero counts + zero rows
    cb_hist<<<2048, 256>>>(row, col);                // histogram only (no prefill)
    cb_blocksum<<<NB_U + NB_I, 1024>>>();
    cb_scan_bsums<<<1, 128>>>();
    cb_scan_final<<<NB_U + NB_I, 1024>>>();          // scan + pad-slot fill
    cb_scatter<<<2048, 256>>>(row, col);             // scatter + scale u0 + u16 mirror

    const int GA = (N_USERS * 16 + 255) / 256;  // half-warp per user row
    const int GI = (N_ITEMS * 16 + 255) / 256;  // half-warp per item row

    // ---- Chebyshev recurrence (scaled domain; fp16 gather, half-warp rows) ----
    cb_spmmA<<<GA, 256>>>();
    cb_spmmAT_first<<<GI, 256>>>(tA, tB, cf[0], cf[1]);
    float* t0p = tA;
    float* t1p = tB;
    for (int k = 2; k <= ORDER; k++) {
        cb_spmmA<<<GA, 256>>>();
        cb_spmmAT_step<<<GI, 256>>>(t1p, t0p, cf[k]);
        float* tmp = t0p; t0p = t1p; t1p = tmp;   // (t0,t1) <- (t1,t2)
    }

    // ---- final transpose to [BATCH, N_ITEMS] ----
    cb_transpose_out<<<tg, tb>>>(out, signal, sumc);
}